// round 1
// baseline (speedup 1.0000x reference)
#include <cuda_runtime.h>

#define BATCH 32
#define TT    1024
#define NIN   512
#define NH    2048
#define NOUT  256

// ---------------- scratch (device globals; no runtime allocation) ----------------
__device__ float    g_w1t[NIN * NH];            // [i][o]
__device__ float    g_w2t[NH * NOUT];           // [i][o]
__device__ unsigned g_mask1[BATCH * TT * (NIN / 32)];   // 16 words / token
__device__ unsigned g_mask2[BATCH * TT * (NH  / 32)];   // 64 words / token
__device__ float    g_cur1[BATCH * TT * NH];    // [b][t][o]
__device__ float    g_cur2[BATCH * TT * NOUT];  // [b][t][o]

// ---------------- transposes ----------------
__global__ void k_transpose_w1(const float* __restrict__ w1) {
    int idx = blockIdx.x * blockDim.x + threadIdx.x;        // over NH*NIN
    if (idx < NH * NIN) {
        int o = idx / NIN, i = idx % NIN;
        g_w1t[i * NH + o] = w1[idx];
    }
}
__global__ void k_transpose_w2(const float* __restrict__ w2) {
    int idx = blockIdx.x * blockDim.x + threadIdx.x;        // over NOUT*NH
    if (idx < NOUT * NH) {
        int o = idx / NH, i = idx % NH;
        g_w2t[i * NOUT + o] = w2[idx];
    }
}

// ---------------- input spike bitmasks ----------------
// x: (B, NIN, T).  One thread per token (b,t); reads coalesced across t.
__global__ void k_mask1(const float* __restrict__ x) {
    int b = blockIdx.y;
    int t = blockIdx.x * blockDim.x + threadIdx.x;          // blockDim = 128
    const float* xb = x + (b * NIN) * TT + t;
    unsigned* mout = &g_mask1[(b * TT + t) * (NIN / 32)];
#pragma unroll
    for (int w = 0; w < NIN / 32; w++) {
        unsigned m = 0;
#pragma unroll
        for (int k = 0; k < 32; k++) {
            float v = xb[(w * 32 + k) * TT];
            m |= (v != 0.0f ? 1u : 0u) << k;
        }
        mout[w] = m;
    }
}

// ---------------- sparse "accumulate rows" GEMM ----------------
// out[b][t][o] = bias[o] + sum_{i active} wT[i][o]
// Block: 128 outputs x 128 tokens. 8 warps, each warp owns 16 tokens, lanes
// cover 128 outputs via float4 (o = o0 + lane*4 + {0..3}).
// Wt is staged per 64-i chunk (32 KB smem). Active i iterated via ffs on masks
// in ascending order (deterministic accumulation order).
template <int IN, int OTOT>
__global__ __launch_bounds__(256) void k_sparse_gemm(
    const float* __restrict__ wT,          // [IN][OTOT]
    const unsigned* __restrict__ masks,    // [B*T][IN/32]
    const float* __restrict__ bias,        // [OTOT]
    float* __restrict__ out)               // [B*T][OTOT]
{
    constexpr int CHUNK = 64;
    constexpr int NW    = IN / 32;
    constexpr int NCH   = IN / CHUNK;
    constexpr int G     = 16;

    __shared__ float    w_s[CHUNK * 128];
    __shared__ unsigned m_s[128 * 2];

    const int tid  = threadIdx.x;
    const int warp = tid >> 5;
    const int lane = tid & 31;
    const int o0   = blockIdx.x * 128;
    const int tok0 = (blockIdx.z * TT) + blockIdx.y * 128;

    float4 acc[G];
#pragma unroll
    for (int g = 0; g < G; g++) acc[g] = make_float4(0.f, 0.f, 0.f, 0.f);

    for (int c = 0; c < NCH; c++) {
        // stage Wt chunk: 64 rows x 128 cols
#pragma unroll
        for (int l = 0; l < (CHUNK * 32) / 256; l++) {      // 8 float4 per thread
            int idx = l * 256 + tid;
            int row = idx >> 5, col = idx & 31;
            float4 v = *(const float4*)&wT[(c * CHUNK + row) * OTOT + o0 + col * 4];
            *(float4*)&w_s[row * 128 + col * 4] = v;
        }
        // stage masks: 128 tokens x 2 words
        {
            int tk = tid >> 1, w = tid & 1;
            m_s[tid] = masks[(tok0 + tk) * NW + c * 2 + w];
        }
        __syncthreads();

#pragma unroll
        for (int g = 0; g < G; g++) {
            const unsigned* mw = &m_s[(warp * G + g) * 2];
#pragma unroll
            for (int w = 0; w < 2; w++) {
                unsigned m = mw[w];
                while (m) {
                    int bit = __ffs(m) - 1;
                    m &= (m - 1);
                    const float4 wv = *(const float4*)&w_s[(w * 32 + bit) * 128 + lane * 4];
                    acc[g].x += wv.x; acc[g].y += wv.y;
                    acc[g].z += wv.z; acc[g].w += wv.w;
                }
            }
        }
        __syncthreads();
    }

    const float4 bv = *(const float4*)&bias[o0 + lane * 4];
#pragma unroll
    for (int g = 0; g < G; g++) {
        float4 r;
        r.x = acc[g].x + bv.x; r.y = acc[g].y + bv.y;
        r.z = acc[g].z + bv.z; r.w = acc[g].w + bv.w;
        *(float4*)&out[(tok0 + warp * G + g) * OTOT + o0 + lane * 4] = r;
    }
}

// ---------------- CUBA-LIF scan ----------------
// cur: [B*T][N] (token-major, coalesced reads). spk: (B, N, T) reference layout.
// Replicates reference arithmetic exactly: v = v*0.95 + c (mul then add),
// s = (v >= 1), v = 0 on spike. Optionally emits layer-2 bitmasks via ballot.
template <int N, int NWTOT, bool MAKE_MASK>
__global__ __launch_bounds__(256) void k_lif(
    const float* __restrict__ cur,
    float* __restrict__ spk,
    unsigned* __restrict__ mask_out)
{
    const int b = blockIdx.y;
    const int o = blockIdx.x * 256 + threadIdx.x;
    const float* cbase = cur + (b * TT) * N + o;
    float* sbase = spk + (b * N + o) * TT;

    float v = 0.0f;
    float r[32];
    for (int tc = 0; tc < TT / 32; tc++) {
#pragma unroll
        for (int k = 0; k < 32; k++) {
            float c = __ldg(&cbase[(tc * 32 + k) * N]);
            v = __fadd_rn(__fmul_rn(v, 0.95f), c);
            bool fire = (v >= 1.0f);
            r[k] = fire ? 1.0f : 0.0f;
            v = fire ? 0.0f : v;
            if (MAKE_MASK) {
                unsigned m = __ballot_sync(0xFFFFFFFFu, fire);
                if ((threadIdx.x & 31) == 0)
                    mask_out[(b * TT + tc * 32 + k) * NWTOT + (o >> 5)] = m;
            }
        }
#pragma unroll
        for (int q = 0; q < 8; q++)
            *(float4*)&sbase[tc * 32 + q * 4] =
                make_float4(r[q * 4], r[q * 4 + 1], r[q * 4 + 2], r[q * 4 + 3]);
    }
}

// ---------------- launch ----------------
extern "C" void kernel_launch(void* const* d_in, const int* in_sizes, int n_in,
                              void* d_out, int out_size) {
    const float* x  = (const float*)d_in[0];   // (B, 512, T)
    const float* w1 = (const float*)d_in[1];   // (2048, 512)
    const float* b1 = (const float*)d_in[2];   // (2048,)
    const float* w2 = (const float*)d_in[3];   // (256, 2048)
    const float* b2 = (const float*)d_in[4];   // (256,)
    float* out = (float*)d_out;
    float* spk1_out = out;                               // (B, 2048, T)
    float* spk2_out = out + (size_t)BATCH * NH * TT;     // (B, 256, T)

    float*    w1t = nullptr; cudaGetSymbolAddress((void**)&w1t, g_w1t);
    float*    w2t = nullptr; cudaGetSymbolAddress((void**)&w2t, g_w2t);
    unsigned* m1  = nullptr; cudaGetSymbolAddress((void**)&m1,  g_mask1);
    unsigned* m2  = nullptr; cudaGetSymbolAddress((void**)&m2,  g_mask2);
    float*    c1  = nullptr; cudaGetSymbolAddress((void**)&c1,  g_cur1);
    float*    c2  = nullptr; cudaGetSymbolAddress((void**)&c2,  g_cur2);

    k_transpose_w1<<<(NH * NIN + 255) / 256, 256>>>(w1);
    k_transpose_w2<<<(NOUT * NH + 255) / 256, 256>>>(w2);
    k_mask1<<<dim3(TT / 128, BATCH), 128>>>(x);

    // layer 1 synapse: cur1 = sparse-accum(w1t, mask1) + b1
    k_sparse_gemm<NIN, NH><<<dim3(NH / 128, TT / 128, BATCH), 256>>>(w1t, m1, b1, c1);
    // layer 1 neuron: spk1 + layer-2 masks
    k_lif<NH, NH / 32, true><<<dim3(NH / 256, BATCH), 256>>>(c1, spk1_out, m2);
    // layer 2 synapse
    k_sparse_gemm<NH, NOUT><<<dim3(NOUT / 128, TT / 128, BATCH), 256>>>(w2t, m2, b2, c2);
    // layer 2 neuron
    k_lif<NOUT, NOUT / 32, false><<<dim3(NOUT / 256, BATCH), 256>>>(c2, spk2_out, nullptr);
}